// round 17
// baseline (speedup 1.0000x reference)
#include <cuda_runtime.h>
#include <cuda_bf16.h>

// Problem constants (fixed by the reference)
#define NNODES 50000
#define NEDGES 800000
#define NFEAT  512
#define NHID   256
#define NLAT   128

// Source-node tiling for L2-blocked SpMM (tiling done inside spmm passes;
// CSR build is the proven non-tiled version)
#define NT   4
#define TSZ  12500                     // NNODES / NT exactly

// ---------------- scratch (device globals; no allocation allowed) -----------
static __device__ float g_C1[(size_t)NNODES * NHID];   // x@W1
static __device__ float g_H [(size_t)NNODES * NHID];   // relu(spmm1+b1)
static __device__ float g_C2[(size_t)NNODES * NLAT];   // h@W2
static __device__ int   g_rowptr[NNODES + 1];
static __device__ int   g_cnt[NNODES];                 // statically zero-initialized
static __device__ int   g_cols[NEDGES];
static __device__ float g_vals[NEDGES];

// ---------------- CSR build (byte-identical to the R10-passing version) -----
// g_cnt is zero at first call (static init) and restored to zero by the
// countdown scatter — graph-replay safe, no zeroing kernel.
__global__ void hist_kernel(const int* __restrict__ rows) {
    int e = blockIdx.x * blockDim.x + threadIdx.x;
    if (e < NEDGES) atomicAdd(&g_cnt[rows[e]], 1);
}

// Single-block exclusive scan of g_cnt -> g_rowptr. Does NOT reset g_cnt
// (degrees are needed as countdown cursors by the scatter).
__global__ void scan_kernel() {
    __shared__ int sums[256];
    int tid = threadIdx.x;
    const int chunk = (NNODES + 255) / 256;
    int s0 = tid * chunk;
    int s1 = min(s0 + chunk, NNODES);
    int s = 0;
    for (int i = s0; i < s1; i++) s += g_cnt[i];
    sums[tid] = s;
    __syncthreads();
    if (tid == 0) {
        int acc = 0;
        for (int i = 0; i < 256; i++) { int t = sums[i]; sums[i] = acc; acc += t; }
        g_rowptr[NNODES] = acc;
    }
    __syncthreads();
    int acc = sums[tid];
    for (int i = s0; i < s1; i++) {
        g_rowptr[i] = acc;
        acc += g_cnt[i];
    }
}

// ---------------- SGEMM core (device fn), 128x128x8, 8x8 microtile ----------
#define GBM 128
#define GBN 128
#define GBK 8

__device__ __forceinline__ void sgemm_device(
    const float* __restrict__ A, const float* __restrict__ B, float* __restrict__ C,
    int M, int N, int K, int bx, int by,
    float (*As)[GBM], float (*Bs)[GBN])
{
    const int tid = threadIdx.x;               // 256 threads
    const int bm = by * GBM;
    const int bn = bx * GBN;

    const int arow = tid >> 1;                 // 0..127
    const int acol = (tid & 1) * 4;            // 0 or 4
    const int brow = tid >> 5;                 // 0..7
    const int bcol = (tid & 31) * 4;           // 0..124

    const int w = tid >> 5, l = tid & 31;
    const int wm = w >> 2, wn = w & 3;
    const int lm = l >> 2, ln = l & 3;
    const int mbase = wm * 64 + lm * 4;        // + {0, 32}
    const int nbase = wn * 32 + ln * 4;        // + {0, 16}

    float acc[8][8];
#pragma unroll
    for (int i = 0; i < 8; i++)
#pragma unroll
        for (int j = 0; j < 8; j++) acc[i][j] = 0.f;

    float4 pa = make_float4(0.f, 0.f, 0.f, 0.f);
    float4 pb;
    {
        int r = bm + arow;
        if (r < M) pa = *(const float4*)&A[(size_t)r * K + acol];
        pb = *(const float4*)&B[(size_t)brow * N + bn + bcol];
    }

    for (int k0 = 0; k0 < K; k0 += GBK) {
        As[acol + 0][arow] = pa.x;
        As[acol + 1][arow] = pa.y;
        As[acol + 2][arow] = pa.z;
        As[acol + 3][arow] = pa.w;
        *(float4*)&Bs[brow][bcol] = pb;
        __syncthreads();

        if (k0 + GBK < K) {
            int r = bm + arow;
            pa = make_float4(0.f, 0.f, 0.f, 0.f);
            if (r < M) pa = *(const float4*)&A[(size_t)r * K + (k0 + GBK) + acol];
            pb = *(const float4*)&B[(size_t)(k0 + GBK + brow) * N + bn + bcol];
        }

#pragma unroll
        for (int k = 0; k < GBK; k++) {
            float4 a0 = *(const float4*)&As[k][mbase];
            float4 a1 = *(const float4*)&As[k][mbase + 32];
            float4 b0 = *(const float4*)&Bs[k][nbase];
            float4 b1 = *(const float4*)&Bs[k][nbase + 16];
            float av[8] = {a0.x, a0.y, a0.z, a0.w, a1.x, a1.y, a1.z, a1.w};
            float bv[8] = {b0.x, b0.y, b0.z, b0.w, b1.x, b1.y, b1.z, b1.w};
#pragma unroll
            for (int i = 0; i < 8; i++)
#pragma unroll
                for (int j = 0; j < 8; j++)
                    acc[i][j] = fmaf(av[i], bv[j], acc[i][j]);
        }
        __syncthreads();
    }

#pragma unroll
    for (int i = 0; i < 8; i++) {
        int m = bm + mbase + ((i < 4) ? i : (32 + i - 4));
        if (m < M) {
            float4 o0 = make_float4(acc[i][0], acc[i][1], acc[i][2], acc[i][3]);
            float4 o1 = make_float4(acc[i][4], acc[i][5], acc[i][6], acc[i][7]);
            *(float4*)&C[(size_t)m * N + bn + nbase] = o0;
            *(float4*)&C[(size_t)m * N + bn + nbase + 16] = o1;
        }
    }
}

__global__ __launch_bounds__(256) void sgemm_kernel(
    const float* __restrict__ A, const float* __restrict__ B, float* __restrict__ C,
    int M, int N, int K)
{
    __shared__ float As[GBK][GBM];
    __shared__ float Bs[GBK][GBN];
    sgemm_device(A, B, C, M, N, K, blockIdx.x, blockIdx.y, As, Bs);
}

// ---------------- fat kernel: gemm1 tiles + countdown scatter ---------------
#define GEMM1_BX (NHID / GBN)                       // 2
#define GEMM1_BY ((NNODES + GBM - 1) / GBM)         // 391
#define GEMM1_BLOCKS (GEMM1_BX * GEMM1_BY)          // 782
#define SCAT_BLOCKS ((NEDGES + 255) / 256)          // 3125

__global__ __launch_bounds__(256) void mega_kernel(
    const float* __restrict__ A, const float* __restrict__ B, float* __restrict__ C,
    const int* __restrict__ rows, const int* __restrict__ cols,
    const float* __restrict__ vals)
{
    __shared__ float As[GBK][GBM];
    __shared__ float Bs[GBK][GBN];
    if (blockIdx.x < GEMM1_BLOCKS) {
        sgemm_device(A, B, C, NNODES, NHID, NFEAT,
                     blockIdx.x % GEMM1_BX, blockIdx.x / GEMM1_BX, As, Bs);
    } else {
        int e = (blockIdx.x - GEMM1_BLOCKS) * 256 + threadIdx.x;
        if (e < NEDGES) {
            int r = rows[e];
            int k = atomicSub(&g_cnt[r], 1) - 1;   // ends at 0 -> replay-safe
            int p = g_rowptr[r] + k;
            g_cols[p] = cols[e];
            g_vals[p] = vals[e];
        }
    }
}

// ---------------- L2-blocked SpMM pass (in-kernel tile filter) ---------------
// Each pass scans the warp's full edge list but only gathers rows in
// [lo, hi): out-of-tile edges have their value masked to 0 and their index
// clamped to lo (a gather of a hot, in-tile row — harmless, branchless).
// All real gathers stay inside a TSZ*d*4-byte window -> L2-resident.
// FIRST: acc starts at 0; otherwise read the partial from out.
// LAST:  fuse bias + relu; otherwise store the raw partial.
template <int NSLICE, bool FIRST, bool LAST>
__global__ __launch_bounds__(256) void spmm_pass(
    const float* __restrict__ dense, const float* __restrict__ bias,
    float* __restrict__ out, int lo, int hi)
{
    int gw = (blockIdx.x * blockDim.x + threadIdx.x) >> 5;
    int lane = threadIdx.x & 31;
    int row = gw / NSLICE;
    int slice = gw % NSLICE;
    if (row >= NNODES) return;
    const int d = NSLICE * 128;
    const int soff = slice * 128 + lane * 4;
    const size_t oidx = (size_t)row * d + soff;

    int beg = __ldg(&g_rowptr[row]);
    int end = __ldg(&g_rowptr[row + 1]);

    float4 acc;
    if (FIRST) acc = make_float4(0.f, 0.f, 0.f, 0.f);
    else       acc = *(const float4*)&out[oidx];

    for (int e = beg; e < end; e += 4) {
        int   c0 = __ldg(&g_cols[e]);
        float v0 = __ldg(&g_vals[e]);
        int   c1 = lo, c2 = lo, c3 = lo;
        float v1 = 0.f, v2 = 0.f, v3 = 0.f;
        if (e + 1 < end) { c1 = __ldg(&g_cols[e + 1]); v1 = __ldg(&g_vals[e + 1]); }
        if (e + 2 < end) { c2 = __ldg(&g_cols[e + 2]); v2 = __ldg(&g_vals[e + 2]); }
        if (e + 3 < end) { c3 = __ldg(&g_cols[e + 3]); v3 = __ldg(&g_vals[e + 3]); }

        // tile filter: mask value, clamp index into the tile
        bool i0 = (c0 >= lo) && (c0 < hi);
        bool i1 = (c1 >= lo) && (c1 < hi);
        bool i2 = (c2 >= lo) && (c2 < hi);
        bool i3 = (c3 >= lo) && (c3 < hi);
        v0 = i0 ? v0 : 0.f;  c0 = i0 ? c0 : lo;
        v1 = i1 ? v1 : 0.f;  c1 = i1 ? c1 : lo;
        v2 = i2 ? v2 : 0.f;  c2 = i2 ? c2 : lo;
        v3 = i3 ? v3 : 0.f;  c3 = i3 ? c3 : lo;

        float4 t0 = __ldg((const float4*)&dense[(size_t)c0 * d + soff]);
        float4 t1 = __ldg((const float4*)&dense[(size_t)c1 * d + soff]);
        float4 t2 = __ldg((const float4*)&dense[(size_t)c2 * d + soff]);
        float4 t3 = __ldg((const float4*)&dense[(size_t)c3 * d + soff]);

        acc.x = fmaf(v0, t0.x, fmaf(v1, t1.x, fmaf(v2, t2.x, fmaf(v3, t3.x, acc.x))));
        acc.y = fmaf(v0, t0.y, fmaf(v1, t1.y, fmaf(v2, t2.y, fmaf(v3, t3.y, acc.y))));
        acc.z = fmaf(v0, t0.z, fmaf(v1, t1.z, fmaf(v2, t2.z, fmaf(v3, t3.z, acc.z))));
        acc.w = fmaf(v0, t0.w, fmaf(v1, t1.w, fmaf(v2, t2.w, fmaf(v3, t3.w, acc.w))));
    }

    if (LAST) {
        float4 b = __ldg((const float4*)&bias[soff]);
        acc.x = fmaxf(acc.x + b.x, 0.f);
        acc.y = fmaxf(acc.y + b.y, 0.f);
        acc.z = fmaxf(acc.z + b.z, 0.f);
        acc.w = fmaxf(acc.w + b.w, 0.f);
    }
    *(float4*)&out[oidx] = acc;
}

// ---------------- launch -----------------------------------------------------
// ncu window hits MY launch index 3 -> spmm1 pass 0 (the key measurement).
extern "C" void kernel_launch(void* const* d_in, const int* in_sizes, int n_in,
                              void* d_out, int out_size)
{
    const float* x    = (const float*)d_in[0];
    const int*   rows = (const int*)  d_in[1];
    const int*   cols = (const int*)  d_in[2];
    const float* vals = (const float*)d_in[3];
    const float* W1   = (const float*)d_in[4];
    const float* b1   = (const float*)d_in[5];
    const float* W2   = (const float*)d_in[6];
    const float* b2   = (const float*)d_in[7];
    float* out = (float*)d_out;

    (void)in_sizes; (void)n_in; (void)out_size;

    // #0: degree histogram (g_cnt zero via static init / countdown restore)
    hist_kernel<<<(NEDGES + 255) / 256, 256>>>(rows);

    // #1: exclusive scan -> rowptr (keeps g_cnt = degrees)
    scan_kernel<<<1, 256>>>();

    // #2: gemm1 (x@W1 -> g_C1) fused with countdown scatter (CSR cols/vals)
    mega_kernel<<<GEMM1_BLOCKS + SCAT_BLOCKS, 256>>>(x, W1, g_C1, rows, cols, vals);

    // #3..#6: H = relu(spmm(C1) + b1), 4 L2-blocked passes (#3 profiled)
    {
        int blocks = (NNODES * 2) / 8;   // 100000 warps, 8 warps/block
        spmm_pass<2, true,  false><<<blocks, 256>>>(g_C1, b1, g_H, 0 * TSZ, 1 * TSZ);
        spmm_pass<2, false, false><<<blocks, 256>>>(g_C1, b1, g_H, 1 * TSZ, 2 * TSZ);
        spmm_pass<2, false, false><<<blocks, 256>>>(g_C1, b1, g_H, 2 * TSZ, 3 * TSZ);
        spmm_pass<2, false, true ><<<blocks, 256>>>(g_C1, b1, g_H, 3 * TSZ, 4 * TSZ);
    }

    // #7: C2 = H @ W2
    {
        dim3 grid(NLAT / GBN, (NNODES + GBM - 1) / GBM);
        sgemm_kernel<<<grid, 256>>>(g_H, W2, g_C2, NNODES, NLAT, NHID);
    }

    // #8..#11: out = relu(spmm(C2) + b2), 4 L2-blocked passes
    {
        int blocks = NNODES / 8;         // 50000 warps / 8 = 6250
        spmm_pass<1, true,  false><<<blocks, 256>>>(g_C2, b2, out, 0 * TSZ, 1 * TSZ);
        spmm_pass<1, false, false><<<blocks, 256>>>(g_C2, b2, out, 1 * TSZ, 2 * TSZ);
        spmm_pass<1, false, false><<<blocks, 256>>>(g_C2, b2, out, 2 * TSZ, 3 * TSZ);
        spmm_pass<1, false, true ><<<blocks, 256>>>(g_C2, b2, out, 3 * TSZ, 4 * TSZ);
    }
}